// round 1
// baseline (speedup 1.0000x reference)
#include <cuda_runtime.h>

// Problem-fixed sizes (from reference setup_inputs).
#define MAX_N_VARS    1000000
#define MAX_N_CONSTRS 1000000

// Scratch (allocs forbidden -> __device__ globals).
__device__ float g_values[MAX_N_VARS];
__device__ float g_ax[MAX_N_CONSTRS];

// ---------------------------------------------------------------------------
// Kernel 1: values = pred*(ub-lb)+lb ; zero ax ; zero out scalar.
// ---------------------------------------------------------------------------
__global__ void prep_kernel(const float* __restrict__ pred,
                            const float* __restrict__ lb,
                            const float* __restrict__ ub,
                            int n_vars, int n_constrs,
                            float* __restrict__ out) {
    int i = blockIdx.x * blockDim.x + threadIdx.x;
    if (i < n_vars) {
        float p = pred[i];
        float l = lb[i];
        float u = ub[i];
        g_values[i] = fmaf(p, u - l, l);
    }
    if (i < n_constrs) g_ax[i] = 0.0f;
    if (i == 0) out[0] = 0.0f;
}

// ---------------------------------------------------------------------------
// Kernel 2: segmented scatter-add. constr_idx is sorted, so accumulate runs
// locally and emit one atomic per run boundary (~2 atomics / 16 items).
// ---------------------------------------------------------------------------
#define ITEMS 16

__global__ void spmv_kernel(const float* __restrict__ coeff,
                            const int*   __restrict__ cidx,
                            const int*   __restrict__ vidx,
                            int nnz) {
    long long base = (long long)(blockIdx.x * blockDim.x + threadIdx.x) * ITEMS;
    if (base >= nnz) return;

    float c[ITEMS];
    int   ci[ITEMS];
    int   vi[ITEMS];
    int   count;

    if (base + ITEMS <= nnz) {
        count = ITEMS;
#pragma unroll
        for (int j = 0; j < ITEMS; j += 4) {
            float4 f = *reinterpret_cast<const float4*>(coeff + base + j);
            int4   a = *reinterpret_cast<const int4*>(cidx + base + j);
            int4   b = *reinterpret_cast<const int4*>(vidx + base + j);
            c[j + 0] = f.x; c[j + 1] = f.y; c[j + 2] = f.z; c[j + 3] = f.w;
            ci[j + 0] = a.x; ci[j + 1] = a.y; ci[j + 2] = a.z; ci[j + 3] = a.w;
            vi[j + 0] = b.x; vi[j + 1] = b.y; vi[j + 2] = b.z; vi[j + 3] = b.w;
        }
    } else {
        count = (int)(nnz - base);
        for (int j = 0; j < count; j++) {
            c[j]  = coeff[base + j];
            ci[j] = cidx[base + j];
            vi[j] = vidx[base + j];
        }
    }

    // Gather values (L2-resident 4MB array) and run-length accumulate.
    float prod[ITEMS];
#pragma unroll
    for (int j = 0; j < ITEMS; j++) {
        if (j < count) prod[j] = c[j] * g_values[vi[j]];
    }

    int   cur = ci[0];
    float acc = prod[0];
#pragma unroll
    for (int j = 1; j < ITEMS; j++) {
        if (j < count) {
            if (ci[j] == cur) {
                acc += prod[j];
            } else {
                atomicAdd(&g_ax[cur], acc);
                cur = ci[j];
                acc = prod[j];
            }
        }
    }
    atomicAdd(&g_ax[cur], acc);
}

// ---------------------------------------------------------------------------
// Kernel 3: violations + mean reduction.
// sense: 1 -> relu(ax-b), 2 -> relu(b-ax), 3 -> |ax-b|, else 0.
// ---------------------------------------------------------------------------
__global__ void loss_kernel(const float* __restrict__ rhs,
                            const int*   __restrict__ sense,
                            int n_constrs, float inv_n,
                            float* __restrict__ out) {
    __shared__ float sdata[32];
    float local = 0.0f;
    int stride = gridDim.x * blockDim.x;
    for (int i = blockIdx.x * blockDim.x + threadIdx.x; i < n_constrs; i += stride) {
        float diff = g_ax[i] - rhs[i];
        int   s    = sense[i];
        float v;
        if (s == 1)      v = fmaxf(diff, 0.0f);
        else if (s == 2) v = fmaxf(-diff, 0.0f);
        else if (s == 3) v = fabsf(diff);
        else             v = 0.0f;
        local += v;
    }
    // warp reduce
#pragma unroll
    for (int off = 16; off > 0; off >>= 1)
        local += __shfl_down_sync(0xffffffffu, local, off);
    int lane = threadIdx.x & 31;
    int wid  = threadIdx.x >> 5;
    if (lane == 0) sdata[wid] = local;
    __syncthreads();
    int nwarps = (blockDim.x + 31) >> 5;
    if (wid == 0) {
        float v = (lane < nwarps) ? sdata[lane] : 0.0f;
#pragma unroll
        for (int off = 16; off > 0; off >>= 1)
            v += __shfl_down_sync(0xffffffffu, v, off);
        if (lane == 0) atomicAdd(out, v * inv_n);
    }
}

// ---------------------------------------------------------------------------
// Launch. Input order (metadata): pred, coeff, constr_rhs, var_lb, var_ub,
// constr_idx, var_idx, constr_sense, n_vars, n_constrs.
// ---------------------------------------------------------------------------
extern "C" void kernel_launch(void* const* d_in, const int* in_sizes, int n_in,
                              void* d_out, int out_size) {
    const float* pred  = (const float*)d_in[0];
    const float* coeff = (const float*)d_in[1];
    const float* rhs   = (const float*)d_in[2];
    const float* lb    = (const float*)d_in[3];
    const float* ub    = (const float*)d_in[4];
    const int*   cidx  = (const int*)d_in[5];
    const int*   vidx  = (const int*)d_in[6];
    const int*   sense = (const int*)d_in[7];

    int n_vars    = in_sizes[0];
    int nnz       = in_sizes[1];
    int n_constrs = in_sizes[2];

    float* out = (float*)d_out;

    int n_max = n_vars > n_constrs ? n_vars : n_constrs;
    int threads = 256;

    prep_kernel<<<(n_max + threads - 1) / threads, threads>>>(
        pred, lb, ub, n_vars, n_constrs, out);

    long long n_threads_spmv = ((long long)nnz + ITEMS - 1) / ITEMS;
    int blocks_spmv = (int)((n_threads_spmv + threads - 1) / threads);
    spmv_kernel<<<blocks_spmv, threads>>>(coeff, cidx, vidx, nnz);

    int blocks_loss = 1184;  // 8 * 148 SMs
    loss_kernel<<<blocks_loss, threads>>>(rhs, sense, n_constrs,
                                          1.0f / (float)n_constrs, out);
}